// round 13
// baseline (speedup 1.0000x reference)
#include <cuda_runtime.h>
#include <cuda_fp16.h>
#include <math.h>
#include <stdint.h>

// ===========================================================================
// MVAEdecoder via HMMA (mma.sync m16n8k16 fp16, fp32 accum), single-term:
//   D[m,o] = sum_{e,k} fp16(bc32[m,e] * a16[m,k]) * w16[e,o,k]   (fp32 acc)
// R13: NO pre-split A' array. Activations are unscaled fp16 [m][IN]; the
// GEMM's A->smem stage does LDG(fp16) -> fp32 scale by bc -> STS, pipelined
// (LDG c+2 before compute(c), STS c+1 at top of iter c). Inner mma loop is
// identical to the R7/R12 champion. Hidden epilogues emit fp16+ELU directly.
// ===========================================================================

#define MB 4096
#define XD 800
#define ZD 64
#define HD 1024
#define OD 768
#define GHD 128
#define NE 8
#define GW (XD + ZD)   // 864
#define HW (HD + ZD)   // 1088

#define KP0 (NE * GW)  // 6912
#define KP1 (NE * HW)  // 8704
#define KP3 (NE * HD)  // 8192

#define BM 256

// ---------------- static device scratch ----------------
__device__ __align__(128) float g_G [MB * GW];     // fp32 concat (gates)
__device__ __align__(128) float g_H1[MB * GHD];
__device__ __align__(128) float g_H2[MB * GHD];
__device__ __align__(128) float g_BC[MB * NE];

__device__ __align__(128) __half g_G16 [MB * GW];  // fp16 concat (L0 input)
__device__ __align__(128) __half g_HA16[MB * HW];  // ping-pong activations
__device__ __align__(128) __half g_HB16[MB * HW];

// fp16 weight copies, layout [Nout][K'=NE*IN]
__device__ __align__(128) __half g_W0h[HD * KP0];
__device__ __align__(128) __half g_W1h[HD * KP1];
__device__ __align__(128) __half g_W2h[HD * KP1];
__device__ __align__(128) __half g_W3h[OD * KP3];

// ---------------- PTX helpers ----------------
__device__ __forceinline__ uint32_t smem_u32(const void* p) {
    uint32_t a;
    asm("{ .reg .u64 t; cvta.to.shared.u64 t, %1; cvt.u32.u64 %0, t; }" : "=r"(a) : "l"(p));
    return a;
}

__device__ __forceinline__ void cp_async16(uint32_t dst, const void* src) {
    asm volatile("cp.async.cg.shared.global [%0], [%1], 16;" :: "r"(dst), "l"(src) : "memory");
}
#define CP_COMMIT() asm volatile("cp.async.commit_group;" ::: "memory")
#define CP_WAIT1()  asm volatile("cp.async.wait_group 1;" ::: "memory")
#define CP_WAIT0()  asm volatile("cp.async.wait_group 0;" ::: "memory")

__device__ __forceinline__ void ldsm4(uint32_t* r, uint32_t addr) {
    asm volatile("ldmatrix.sync.aligned.m8n8.x4.shared.b16 {%0,%1,%2,%3}, [%4];"
                 : "=r"(r[0]), "=r"(r[1]), "=r"(r[2]), "=r"(r[3]) : "r"(addr));
}

__device__ __forceinline__ void mma16816(float* c, const uint32_t* a, const uint32_t* b) {
    asm volatile(
        "mma.sync.aligned.m16n8k16.row.col.f32.f16.f16.f32 "
        "{%0,%1,%2,%3}, {%4,%5,%6,%7}, {%8,%9}, {%0,%1,%2,%3};"
        : "+f"(c[0]), "+f"(c[1]), "+f"(c[2]), "+f"(c[3])
        : "r"(a[0]), "r"(a[1]), "r"(a[2]), "r"(a[3]), "r"(b[0]), "r"(b[1]));
}

// scale a packed half2 (as u32) by fp32 s, round back to half2
__device__ __forceinline__ uint32_t h2scale(uint32_t u, float s) {
    __half2 h = *reinterpret_cast<__half2*>(&u);
    float2 f = __half22float2(h);
    __half2 r = __floats2half2_rn(f.x * s, f.y * s);
    return *reinterpret_cast<uint32_t*>(&r);
}

// ===========================================================================
// prep: G fp32 + G16 fp16 = concat(x,z); fp16 z-cols of HA16/HB16
// ===========================================================================
__global__ void prep_kernel(const float* __restrict__ x, const float* __restrict__ z,
                            float* __restrict__ G, __half* __restrict__ G16,
                            __half* __restrict__ HA16, __half* __restrict__ HB16) {
    int i = blockIdx.x * blockDim.x + threadIdx.x;
    const int totG = MB * GW;
    if (i < totG) {
        int b = i / GW, c = i - b * GW;
        float v = (c < XD) ? x[b * XD + c] : z[b * ZD + (c - XD)];
        G[i] = v;
        G16[i] = __float2half_rn(v);
    }
    const int totZ = MB * ZD;
    if (i < totZ) {
        int b = i / ZD, c = i - b * ZD;
        __half v = __float2half_rn(z[i]);
        HA16[b * HW + HD + c] = v;
        HB16[b * HW + HD + c] = v;
    }
}

// ===========================================================================
// W convert: W[e][o][kin] (fp32) -> Wh[o][e*IN+kin] (fp16)
// ===========================================================================
__global__ void wconv_kernel(const float* __restrict__ W,
                             __half* __restrict__ Wh, int Nout, int IN) {
    long long idx = (long long)blockIdx.x * blockDim.x + threadIdx.x;
    long long tot4 = (long long)NE * Nout * IN / 4;
    if (idx >= tot4) return;
    long long i = idx * 4;
    int e = (int)(i / ((long long)Nout * IN));
    long long rem = i - (long long)e * Nout * IN;
    int o = (int)(rem / IN);
    int kin = (int)(rem - (long long)o * IN);
    float4 v = *reinterpret_cast<const float4*>(W + i);
    long long d = (long long)o * ((long long)NE * IN) + e * IN + kin;
    unsigned short h[4];
    h[0] = __half_as_ushort(__float2half_rn(v.x));
    h[1] = __half_as_ushort(__float2half_rn(v.y));
    h[2] = __half_as_ushort(__float2half_rn(v.z));
    h[3] = __half_as_ushort(__float2half_rn(v.w));
    uint2 hp;
    hp.x = ((uint32_t)h[1] << 16) | h[0]; hp.y = ((uint32_t)h[3] << 16) | h[2];
    *reinterpret_cast<uint2*>(Wh + d) = hp;
}

// ===========================================================================
// HMMA GEMM, templated on NWN (32-col N warps). BM=256, BN=32*NWN,
// threads = 128*NWN (warps: 4(M) x NWN(N), warp tile 64x32).
// A path: LDG fp16 [m][kin] + fp32 bc scale + STS (pipelined, 2 slots).
// W path: cp.async 2-stage (unchanged from champion).
// ===========================================================================
template <int NWN>
__global__ __launch_bounds__(128 * NWN, 1)
void moe_hmma_gemm(const __half* __restrict__ A16, int lda, int IN, int Kp,
                   const __half* __restrict__ Wh,
                   const float* __restrict__ bias,  // [NE][Nout]
                   const float* __restrict__ bc,    // [MB][NE]
                   int Nout,
                   __half* __restrict__ C16, int ldc16,  // hidden out (+ELU)
                   float* __restrict__ C32, int ldc32)   // final out
{
    constexpr int NTH = 128 * NWN;
    constexpr int BN = 32 * NWN;
    constexpr int ASEG = (2048 + NTH - 1) / NTH;        // A segs per thread
    constexpr uint32_t W_STAGE = (uint32_t)BN * 128u;
    constexpr int SW_OFF = 65536;                       // after 2 x 32768 A
    constexpr int SBC_OFF = SW_OFF + 2 * (int)W_STAGE;
    constexpr int SBIAS_OFF = SBC_OFF + 8192;

    extern __shared__ char smem[];
    const uint32_t sb = smem_u32(smem);
    const int tid = threadIdx.x;
    const int lane = tid & 31;
    const int wid = tid >> 5;
    const int wm = wid & 3;
    const int wn = wid >> 2;
    const int mBase = blockIdx.y * BM;
    const int nBase = blockIdx.x * BN;
    const int NC = Kp >> 6;

    float* bcs    = reinterpret_cast<float*>(smem + SBC_OFF);   // [256][8]
    float* bias_s = reinterpret_cast<float*>(smem + SBIAS_OFF); // [8][BN]
#pragma unroll
    for (int t = 0; t < (512 + NTH - 1) / NTH; t++) {
        int j = tid + t * NTH;
        if (j < 512)
            reinterpret_cast<float4*>(bcs)[j] =
                reinterpret_cast<const float4*>(bc + (size_t)mBase * NE)[j];
    }
    if (tid < 2 * BN) {
        int e = tid / (BN / 4), cs = (tid % (BN / 4)) << 2;
        reinterpret_cast<float4*>(bias_s + e * BN + cs)[0] =
            reinterpret_cast<const float4*>(bias + (size_t)e * Nout + nBase + cs)[0];
    }

    // ---- A loaders ----
    uint4 abuf[ASEG];
    auto ldg_a = [&](int kc) {
#pragma unroll
        for (int i = 0; i < ASEG; i++) {
            int lin = tid + i * NTH;
            if (lin < 2048) {
                int r = lin >> 3, ks = lin & 7;
                int kpos = kc + ks * 8;
                int e = kpos / IN;
                int kin = kpos - e * IN;
                abuf[i] = *reinterpret_cast<const uint4*>(
                    A16 + (size_t)(mBase + r) * lda + kin);
            }
        }
    };
    auto sts_a = [&](int kc, int slot) {
#pragma unroll
        for (int i = 0; i < ASEG; i++) {
            int lin = tid + i * NTH;
            if (lin < 2048) {
                int r = lin >> 3, ks = lin & 7;
                int kpos = kc + ks * 8;
                int e = kpos / IN;
                float s = bcs[r * 8 + e];
                uint4 v = abuf[i];
                uint4 o;
                o.x = h2scale(v.x, s); o.y = h2scale(v.y, s);
                o.z = h2scale(v.z, s); o.w = h2scale(v.w, s);
                uint32_t dstOff = (uint32_t)slot * 32768u + (uint32_t)r * 128u +
                                  (((uint32_t)ks * 16u) ^ (((uint32_t)r & 7u) << 4));
                *reinterpret_cast<uint4*>(smem + dstOff) = o;
            }
        }
    };
    auto load_w = [&](uint32_t wDst, int kc) {
#pragma unroll
        for (int i = 0; i < (BN * 8) / NTH; i++) {
            int lin = tid + i * NTH;
            int o = lin >> 3, ks = lin & 7;
            const __half* src = Wh + (size_t)(nBase + o) * Kp + kc + ks * 8;
            uint32_t dst = wDst + (uint32_t)o * 128u +
                           (((uint32_t)ks * 16u) ^ (((uint32_t)o & 7u) << 4));
            cp_async16(dst, src);
        }
    };

    // ---- prologue ----
    load_w(sb + SW_OFF, 0);
    CP_COMMIT();
    load_w(sb + SW_OFF + W_STAGE, 64);
    CP_COMMIT();
    ldg_a(0);
    __syncthreads();                 // bcs/bias visible
    sts_a(0, 0);                     // A chunk0 -> slot0
    ldg_a(64);                       // A chunk1 -> regs
    CP_WAIT1();                      // W chunk0 arrived
    __syncthreads();                 // A slot0 + W visible

    float acc[4][4][4];
#pragma unroll
    for (int a = 0; a < 4; a++)
#pragma unroll
        for (int b = 0; b < 4; b++)
#pragma unroll
            for (int q = 0; q < 4; q++) acc[a][b][q] = 0.f;

    const int aRow = wm * 64 + (lane & 15);
    const uint32_t aXor = ((uint32_t)aRow & 7u) << 4;
    const uint32_t aKb = ((uint32_t)lane >> 4) << 4;
    const uint32_t aRowOff = (uint32_t)aRow * 128u;
    const int bRow = wn * 32 + (lane & 7) + (((lane >> 4) & 1) << 3);
    const uint32_t bXor = ((uint32_t)bRow & 7u) << 4;
    const uint32_t bKb = (((uint32_t)lane >> 3) & 1u) << 4;
    const uint32_t bRowOff = (uint32_t)bRow * 128u;

    for (int c = 0; c < NC; c++) {
        const int st = c & 1;
        const uint32_t aSt = sb + (uint32_t)st * 32768u;
        const uint32_t wSt = sb + SW_OFF + (uint32_t)st * W_STAGE;

        // stage A chunk c+1 (regs -> free slot), start LDG of chunk c+2
        if (c + 1 < NC) sts_a((c + 1) * 64, (c + 1) & 1);
        if (c + 2 < NC) ldg_a((c + 2) * 64);

#pragma unroll
        for (int kk = 0; kk < 4; kk++) {
            const uint32_t kA = ((uint32_t)(kk * 32) + aKb) ^ aXor;
            const uint32_t kB = ((uint32_t)(kk * 32) + bKb) ^ bXor;
            uint32_t bfh[8], af[4][4];
#pragma unroll
            for (int g = 0; g < 2; g++)
                ldsm4(&bfh[4 * g], wSt + bRowOff + (uint32_t)g * 2048u + kB);
#pragma unroll
            for (int mf = 0; mf < 4; mf++)
                ldsm4(af[mf], aSt + aRowOff + (uint32_t)mf * 2048u + kA);
#pragma unroll
            for (int mf = 0; mf < 4; mf++)
#pragma unroll
                for (int nf = 0; nf < 4; nf++)
                    mma16816(acc[mf][nf], af[mf], &bfh[2 * nf]);
        }

        __syncthreads();
        if (c + 2 < NC) {
            load_w(wSt, (c + 2) * 64);
            CP_COMMIT();
            CP_WAIT1();
        } else {
            CP_WAIT0();
        }
        __syncthreads();
    }

    // ---- epilogue: blended bias; hidden -> fp16+ELU, final -> fp32 ----
#pragma unroll
    for (int mf = 0; mf < 4; mf++) {
        const int r0 = wm * 64 + mf * 16 + (lane >> 2);
        const int r1 = r0 + 8;
        float bcv0[NE], bcv1[NE];
#pragma unroll
        for (int e = 0; e < NE; e++) { bcv0[e] = bcs[r0 * 8 + e]; bcv1[e] = bcs[r1 * 8 + e]; }
#pragma unroll
        for (int nf = 0; nf < 4; nf++) {
            const int cl = wn * 32 + nf * 8 + ((lane & 3) << 1);
            float bb00 = 0.f, bb01 = 0.f, bb10 = 0.f, bb11 = 0.f;
#pragma unroll
            for (int e = 0; e < NE; e++) {
                float be0 = bias_s[e * BN + cl], be1 = bias_s[e * BN + cl + 1];
                bb00 = fmaf(bcv0[e], be0, bb00);
                bb01 = fmaf(bcv0[e], be1, bb01);
                bb10 = fmaf(bcv1[e], be0, bb10);
                bb11 = fmaf(bcv1[e], be1, bb11);
            }
            float v00 = acc[mf][nf][0] + bb00;
            float v01 = acc[mf][nf][1] + bb01;
            float v10 = acc[mf][nf][2] + bb10;
            float v11 = acc[mf][nf][3] + bb11;
            const int gc = nBase + cl;
            if (C32) {
                *reinterpret_cast<float2*>(C32 + (size_t)(mBase + r0) * ldc32 + gc) =
                    make_float2(v00, v01);
                *reinterpret_cast<float2*>(C32 + (size_t)(mBase + r1) * ldc32 + gc) =
                    make_float2(v10, v11);
            } else {
                v00 = (v00 > 0.f) ? v00 : expm1f(v00);
                v01 = (v01 > 0.f) ? v01 : expm1f(v01);
                v10 = (v10 > 0.f) ? v10 : expm1f(v10);
                v11 = (v11 > 0.f) ? v11 : expm1f(v11);
                *reinterpret_cast<__half2*>(C16 + (size_t)(mBase + r0) * ldc16 + gc) =
                    __floats2half2_rn(v00, v01);
                *reinterpret_cast<__half2*>(C16 + (size_t)(mBase + r1) * ldc16 + gc) =
                    __floats2half2_rn(v10, v11);
            }
        }
    }
}

// ===========================================================================
// gate GEMM: BM=32, BN=128(=Nout), BK=16, elu. grid = 4096/32 = 128
// ===========================================================================
__global__ __launch_bounds__(256, 4)
void gate_gemm_kernel(const float* __restrict__ A, int IN,
                      const float* __restrict__ W,   // [128][IN]
                      const float* __restrict__ bias,
                      float* __restrict__ C) {
    __shared__ float As[16][32];
    __shared__ float Bs[16][128];
    const int tid = threadIdx.x;
    const int tx = tid & 15, ty = tid >> 4;
    const int mBase = blockIdx.x * 32;

    float acc[2][8];
#pragma unroll
    for (int i = 0; i < 2; i++)
#pragma unroll
        for (int j = 0; j < 8; j++) acc[i][j] = 0.f;

    const int r2 = tid >> 2;
    const int vec = (tid & 3) << 2;

    for (int k0 = 0; k0 < IN; k0 += 16) {
        if (tid < 128) {
            int r = tid >> 2;
            float4 v = *reinterpret_cast<const float4*>(A + (size_t)(mBase + r) * IN + k0 + vec);
            As[vec + 0][r] = v.x; As[vec + 1][r] = v.y;
            As[vec + 2][r] = v.z; As[vec + 3][r] = v.w;
        }
#pragma unroll
        for (int rr = 0; rr < 2; rr++) {
            int o = r2 + rr * 64;
            float4 v = *reinterpret_cast<const float4*>(W + (size_t)o * IN + k0 + vec);
            Bs[vec + 0][o] = v.x; Bs[vec + 1][o] = v.y;
            Bs[vec + 2][o] = v.z; Bs[vec + 3][o] = v.w;
        }
        __syncthreads();
#pragma unroll
        for (int k = 0; k < 16; k++) {
            float a0 = As[k][ty * 2], a1 = As[k][ty * 2 + 1];
            float4 b0 = *reinterpret_cast<const float4*>(&Bs[k][tx * 8]);
            float4 b1 = *reinterpret_cast<const float4*>(&Bs[k][tx * 8 + 4]);
            float bv[8] = {b0.x, b0.y, b0.z, b0.w, b1.x, b1.y, b1.z, b1.w};
#pragma unroll
            for (int j = 0; j < 8; j++) {
                acc[0][j] = fmaf(a0, bv[j], acc[0][j]);
                acc[1][j] = fmaf(a1, bv[j], acc[1][j]);
            }
        }
        __syncthreads();
    }
#pragma unroll
    for (int i = 0; i < 2; i++) {
        int grow = mBase + ty * 2 + i;
#pragma unroll
        for (int j = 0; j < 8; j++) {
            int gcol = tx * 8 + j;
            float v = acc[i][j] + __ldg(bias + gcol);
            v = (v > 0.f) ? v : expm1f(v);
            C[(size_t)grow * GHD + gcol] = v;
        }
    }
}

// ===========================================================================
// gate3 + softmax (one warp per row)
// ===========================================================================
__global__ void gate3_softmax_kernel(const float* __restrict__ H2,
                                     const float* __restrict__ Wg3,
                                     const float* __restrict__ bg3,
                                     float* __restrict__ BC) {
    int warp = (blockIdx.x * blockDim.x + threadIdx.x) >> 5;
    int lane = threadIdx.x & 31;
    if (warp >= MB) return;
    const float* h = H2 + (size_t)warp * GHD;
    float hv[4];
#pragma unroll
    for (int t = 0; t < 4; t++) hv[t] = h[lane + 32 * t];
    float s[NE];
#pragma unroll
    for (int e = 0; e < NE; e++) {
        float p = 0.f;
#pragma unroll
        for (int t = 0; t < 4; t++)
            p = fmaf(hv[t], __ldg(Wg3 + e * GHD + lane + 32 * t), p);
#pragma unroll
        for (int off = 16; off > 0; off >>= 1) p += __shfl_xor_sync(0xFFFFFFFFu, p, off);
        s[e] = p + __ldg(bg3 + e);
    }
    float mx = s[0];
#pragma unroll
    for (int e = 1; e < NE; e++) mx = fmaxf(mx, s[e]);
    float sum = 0.f;
#pragma unroll
    for (int e = 0; e < NE; e++) { s[e] = expf(s[e] - mx); sum += s[e]; }
    float inv = 1.f / sum;
    if (lane < NE) BC[(size_t)warp * NE + lane] = s[lane] * inv;
}

// ===========================================================================
extern "C" void kernel_launch(void* const* d_in, const int* in_sizes, int n_in,
                              void* d_out, int out_size) {
    const float* x   = (const float*)d_in[0];
    const float* z   = (const float*)d_in[1];
    const float* Wg1 = (const float*)d_in[2];
    const float* bg1 = (const float*)d_in[3];
    const float* Wg2 = (const float*)d_in[4];
    const float* bg2 = (const float*)d_in[5];
    const float* Wg3 = (const float*)d_in[6];
    const float* bg3 = (const float*)d_in[7];
    const float* W0  = (const float*)d_in[8];
    const float* b0  = (const float*)d_in[9];
    const float* W1  = (const float*)d_in[10];
    const float* b1  = (const float*)d_in[11];
    const float* W2  = (const float*)d_in[12];
    const float* b2  = (const float*)d_in[13];
    const float* W3  = (const float*)d_in[14];
    const float* b3  = (const float*)d_in[15];
    float* out = (float*)d_out;

    float *G, *H1, *H2, *BC;
    __half *G16, *HA16, *HB16, *W0h, *W1h, *W2h, *W3h;
    cudaGetSymbolAddress((void**)&G,  g_G);
    cudaGetSymbolAddress((void**)&H1, g_H1);
    cudaGetSymbolAddress((void**)&H2, g_H2);
    cudaGetSymbolAddress((void**)&BC, g_BC);
    cudaGetSymbolAddress((void**)&G16,  g_G16);
    cudaGetSymbolAddress((void**)&HA16, g_HA16);
    cudaGetSymbolAddress((void**)&HB16, g_HB16);
    cudaGetSymbolAddress((void**)&W0h, g_W0h);
    cudaGetSymbolAddress((void**)&W1h, g_W1h);
    cudaGetSymbolAddress((void**)&W2h, g_W2h);
    cudaGetSymbolAddress((void**)&W3h, g_W3h);

    // smem: NWN=4: 65536 + 65536 + 8192 + 4096 = 143360
    //       NWN=3: 65536 + 24576 + 8192 + 3072 = 101376
    cudaFuncSetAttribute(moe_hmma_gemm<4>, cudaFuncAttributeMaxDynamicSharedMemorySize, 143360);
    cudaFuncSetAttribute(moe_hmma_gemm<3>, cudaFuncAttributeMaxDynamicSharedMemorySize, 101376);

    // prep + gate network
    prep_kernel<<<(MB * GW + 255) / 256, 256>>>(x, z, G, G16, HA16, HB16);
    gate_gemm_kernel<<<MB / 32, 256>>>(G, GW, Wg1, bg1, H1);
    gate_gemm_kernel<<<MB / 32, 256>>>(H1, GHD, Wg2, bg2, H2);
    gate3_softmax_kernel<<<(MB * 32 + 255) / 256, 256>>>(H2, Wg3, bg3, BC);

    // layer 0: A16 = G16 [MB,864], IN=864, Kp=6912 -> HA16[:, :1024] fp16+ELU
    {
        long long t0 = (long long)NE * HD * GW / 4;
        wconv_kernel<<<(unsigned)((t0 + 255) / 256), 256>>>(W0, W0h, HD, GW);
        moe_hmma_gemm<4><<<dim3(HD / 128, MB / BM), 512, 143360>>>(
            G16, GW, GW, KP0, W0h, b0, BC, HD, HA16, HW, nullptr, 0);
    }
    // layer 1: A16 = HA16 [MB,1088], IN=1088, Kp=8704 -> HB16
    {
        long long t1 = (long long)NE * HD * HW / 4;
        wconv_kernel<<<(unsigned)((t1 + 255) / 256), 256>>>(W1, W1h, HD, HW);
        moe_hmma_gemm<4><<<dim3(HD / 128, MB / BM), 512, 143360>>>(
            HA16, HW, HW, KP1, W1h, b1, BC, HD, HB16, HW, nullptr, 0);
    }
    // layer 2: HB16 -> HA16
    {
        long long t1 = (long long)NE * HD * HW / 4;
        wconv_kernel<<<(unsigned)((t1 + 255) / 256), 256>>>(W2, W2h, HD, HW);
        moe_hmma_gemm<4><<<dim3(HD / 128, MB / BM), 512, 143360>>>(
            HB16, HW, HW, KP1, W2h, b2, BC, HD, HA16, HW, nullptr, 0);
    }
    // layer 3: A16 = HA16 cols 0..1023 (lda=1088, IN=1024), Kp=8192 -> out fp32
    // BN=96 variant: grid 8x16 = 128 CTAs
    {
        long long t3 = (long long)NE * OD * HD / 4;
        wconv_kernel<<<(unsigned)((t3 + 255) / 256), 256>>>(W3, W3h, OD, HD);
        moe_hmma_gemm<3><<<dim3(OD / 96, MB / BM), 384, 101376>>>(
            HA16, HW, HD, KP3, W3h, b3, BC, OD, nullptr, 0, out, OD);
    }
}

// round 14
// speedup vs baseline: 1.2599x; 1.2599x over previous
#include <cuda_runtime.h>
#include <cuda_fp16.h>
#include <math.h>
#include <stdint.h>

// ===========================================================================
// MVAEdecoder via HMMA (mma.sync m16n8k16 fp16, fp32 accum), single-term:
//   D = fp16(bc*a) @ fp16(W)^T   (fp32 accumulate)
// blend(bc,inp,W,b) => GEMM with K' = E*IN; A'[m,e*IN+k] = bc[m,e]*inp[m,k].
// R14 = R12 champion GEMM (BN=128 L0-2, BN=96 L3) + division-free streaming
// passes: asplit reads each A segment ONCE (e-loop in thread, 8x less read),
// wconv uses a 3D grid (no div/mod). GEMM mainloop untouched.
// ===========================================================================

#define MB 4096
#define XD 800
#define ZD 64
#define HD 1024
#define OD 768
#define GHD 128
#define NE 8
#define GW (XD + ZD)   // 864
#define HW (HD + ZD)   // 1088

#define KP0 (NE * GW)  // 6912
#define KP1 (NE * HW)  // 8704
#define KP3 (NE * HD)  // 8192

#define BM 256

// ---------------- static device scratch ----------------
__device__ __align__(128) float g_G [MB * GW];
__device__ __align__(128) float g_H1[MB * GHD];
__device__ __align__(128) float g_H2[MB * GHD];
__device__ __align__(128) float g_BC[MB * NE];
__device__ __align__(128) float g_HA[MB * HW];
__device__ __align__(128) float g_HB[MB * HW];

// pre-split A' (bc-scaled, expert-replicated), fp16, max K' = 8704
__device__ __align__(128) __half g_Ah[MB * KP1];

// fp16 weight copies, layout [Nout][K'=NE*IN]
__device__ __align__(128) __half g_W0h[HD * KP0];
__device__ __align__(128) __half g_W1h[HD * KP1];
__device__ __align__(128) __half g_W2h[HD * KP1];
__device__ __align__(128) __half g_W3h[OD * KP3];

// ---------------- PTX helpers ----------------
__device__ __forceinline__ uint32_t smem_u32(const void* p) {
    uint32_t a;
    asm("{ .reg .u64 t; cvta.to.shared.u64 t, %1; cvt.u32.u64 %0, t; }" : "=r"(a) : "l"(p));
    return a;
}

__device__ __forceinline__ void cp_async16(uint32_t dst, const void* src) {
    asm volatile("cp.async.cg.shared.global [%0], [%1], 16;" :: "r"(dst), "l"(src) : "memory");
}
#define CP_COMMIT() asm volatile("cp.async.commit_group;" ::: "memory")
#define CP_WAIT1()  asm volatile("cp.async.wait_group 1;" ::: "memory")
#define CP_WAIT0()  asm volatile("cp.async.wait_group 0;" ::: "memory")

__device__ __forceinline__ void ldsm4(uint32_t* r, uint32_t addr) {
    asm volatile("ldmatrix.sync.aligned.m8n8.x4.shared.b16 {%0,%1,%2,%3}, [%4];"
                 : "=r"(r[0]), "=r"(r[1]), "=r"(r[2]), "=r"(r[3]) : "r"(addr));
}

__device__ __forceinline__ void mma16816(float* c, const uint32_t* a, const uint32_t* b) {
    asm volatile(
        "mma.sync.aligned.m16n8k16.row.col.f32.f16.f16.f32 "
        "{%0,%1,%2,%3}, {%4,%5,%6,%7}, {%8,%9}, {%0,%1,%2,%3};"
        : "+f"(c[0]), "+f"(c[1]), "+f"(c[2]), "+f"(c[3])
        : "r"(a[0]), "r"(a[1]), "r"(a[2]), "r"(a[3]), "r"(b[0]), "r"(b[1]));
}

// ===========================================================================
// prep: G = concat(x,z); fill z-cols of HA/HB
// ===========================================================================
__global__ void prep_kernel(const float* __restrict__ x, const float* __restrict__ z,
                            float* __restrict__ G, float* __restrict__ HA,
                            float* __restrict__ HB) {
    int i = blockIdx.x * blockDim.x + threadIdx.x;
    const int totG = MB * GW;
    if (i < totG) {
        int b = i / GW, c = i - b * GW;
        G[i] = (c < XD) ? x[b * XD + c] : z[b * ZD + (c - XD)];
    }
    const int totZ = MB * ZD;
    if (i < totZ) {
        int b = i / ZD, c = i - b * ZD;
        float v = z[i];
        HA[b * HW + HD + c] = v;
        HB[b * HW + HD + c] = v;
    }
}

// ===========================================================================
// W convert (division-free): grid = (ceil(IN/4/256), Nout, NE)
// W[e][o][kin] fp32 -> Wh[o][e*IN+kin] fp16
// ===========================================================================
__global__ void wconv_kernel(const float* __restrict__ W,
                             __half* __restrict__ Wh, int Nout, int IN) {
    int kin = (blockIdx.x * blockDim.x + threadIdx.x) << 2;
    if (kin >= IN) return;
    int o = blockIdx.y;
    int e = blockIdx.z;
    float4 v = *reinterpret_cast<const float4*>(
        W + ((size_t)e * Nout + o) * IN + kin);
    unsigned short h[4];
    h[0] = __half_as_ushort(__float2half_rn(v.x));
    h[1] = __half_as_ushort(__float2half_rn(v.y));
    h[2] = __half_as_ushort(__float2half_rn(v.z));
    h[3] = __half_as_ushort(__float2half_rn(v.w));
    uint2 hp;
    hp.x = ((uint32_t)h[1] << 16) | h[0];
    hp.y = ((uint32_t)h[3] << 16) | h[2];
    *reinterpret_cast<uint2*>(Wh + (size_t)o * (NE * IN) + e * IN + kin) = hp;
}

// ===========================================================================
// A split (division-free, A read once): grid = (ceil(IN/8/128), MB), 128 thr
// Each thread: one 8-elem A segment -> 8 scaled fp16 stores (one per expert).
// bc row is uniform across the block (m = blockIdx.y) -> broadcast loads.
// ===========================================================================
__global__ __launch_bounds__(128)
void asplit_kernel(const float* __restrict__ A, int lda, int IN,
                   const float* __restrict__ bc,
                   __half* __restrict__ Ah, int Kp) {
    int kin = (blockIdx.x * blockDim.x + threadIdx.x) << 3;
    if (kin >= IN) return;
    const int m = blockIdx.y;
    const float* src = A + (size_t)m * lda + kin;
    float4 v0 = *reinterpret_cast<const float4*>(src);
    float4 v1 = *reinterpret_cast<const float4*>(src + 4);
    float a[8] = {v0.x, v0.y, v0.z, v0.w, v1.x, v1.y, v1.z, v1.w};
    __half* dst = Ah + (size_t)m * Kp + kin;
#pragma unroll
    for (int e = 0; e < NE; e++) {
        float sc = __ldg(bc + m * NE + e);
        uint32_t hp[4];
#pragma unroll
        for (int j = 0; j < 4; j++) {
            __half h0 = __float2half_rn(a[2 * j] * sc);
            __half h1 = __float2half_rn(a[2 * j + 1] * sc);
            hp[j] = ((uint32_t)__half_as_ushort(h1) << 16) | __half_as_ushort(h0);
        }
        *reinterpret_cast<uint4*>(dst + e * IN) = make_uint4(hp[0], hp[1], hp[2], hp[3]);
    }
}

// ===========================================================================
// HMMA GEMM, templated on NWN (number of 32-col N warps).
// BM=256, BN=32*NWN, BK=64, threads = 128*NWN (warps: 4(M) x NWN(N),
// warp tile 64x32). Single term, fp32 accumulate, 2-stage cp.async.
// NWN=4 -> R7-identical geometry. NWN=3 -> BN=96 for the 768-wide layer.
// ===========================================================================
template <int NWN>
__global__ __launch_bounds__(128 * NWN, 1)
void moe_hmma_gemm(const __half* __restrict__ Ah, const __half* __restrict__ Wh,
                   int Kp,
                   const float* __restrict__ bias,  // [NE][Nout]
                   const float* __restrict__ bc,    // [MB][NE]
                   int Nout, float* __restrict__ C, int ldc, int applyElu)
{
    constexpr int NTH = 128 * NWN;
    constexpr int BN = 32 * NWN;
    constexpr uint32_t W_STAGE = (uint32_t)BN * 128u;   // bytes per W stage
    constexpr int SW_OFF = 65536;                       // after 2 x 32768 A stages
    constexpr int SBC_OFF = SW_OFF + 2 * (int)W_STAGE;
    constexpr int SBIAS_OFF = SBC_OFF + 8192;

    extern __shared__ char smem[];
    const uint32_t sb = smem_u32(smem);
    const int tid = threadIdx.x;
    const int lane = tid & 31;
    const int wid = tid >> 5;
    const int wm = wid & 3;       // 0..3 along M (64 rows each)
    const int wn = wid >> 2;      // 0..NWN-1 along N (32 cols each)
    const int mBase = blockIdx.y * BM;
    const int nBase = blockIdx.x * BN;
    const int NC = Kp >> 6;

    float* bcs    = reinterpret_cast<float*>(smem + SBC_OFF);   // [256][8]
    float* bias_s = reinterpret_cast<float*>(smem + SBIAS_OFF); // [8][BN]
#pragma unroll
    for (int t = 0; t < (512 + NTH - 1) / NTH; t++) {
        int j = tid + t * NTH;
        if (j < 512)
            reinterpret_cast<float4*>(bcs)[j] =
                reinterpret_cast<const float4*>(bc + (size_t)mBase * NE)[j];
    }
    if (tid < 2 * BN) {   // 8*BN floats / 4
        int e = tid / (BN / 4), cs = (tid % (BN / 4)) << 2;
        reinterpret_cast<float4*>(bias_s + e * BN + cs)[0] =
            reinterpret_cast<const float4*>(bias + (size_t)e * Nout + nBase + cs)[0];
    }

    // ---- chunk loader ----
    auto load_chunk = [&](uint32_t aDst, uint32_t wDst, int kc) {
#pragma unroll
        for (int i = 0; i < (2048 + NTH - 1) / NTH; i++) {
            int lin = tid + i * NTH;          // 256 rows x 8 segs
            if (lin < 2048) {
                int r = lin >> 3, ks = lin & 7;
                const __half* src = Ah + (size_t)(mBase + r) * Kp + kc + ks * 8;
                uint32_t dst = aDst + (uint32_t)r * 128u +
                               (((uint32_t)ks * 16u) ^ (((uint32_t)r & 7u) << 4));
                cp_async16(dst, src);
            }
        }
#pragma unroll
        for (int i = 0; i < (BN * 8) / NTH; i++) {
            int lin = tid + i * NTH;          // BN rows x 8 segs
            int o = lin >> 3, ks = lin & 7;
            const __half* src = Wh + (size_t)(nBase + o) * Kp + kc + ks * 8;
            uint32_t dst = wDst + (uint32_t)o * 128u +
                           (((uint32_t)ks * 16u) ^ (((uint32_t)o & 7u) << 4));
            cp_async16(dst, src);
        }
    };

    // prologue: stage chunks 0 and 1
    load_chunk(sb + 0u, sb + SW_OFF, 0);
    CP_COMMIT();
    load_chunk(sb + 32768u, sb + SW_OFF + W_STAGE, 64);
    CP_COMMIT();
    CP_WAIT1();
    __syncthreads();

    float acc[4][4][4];
#pragma unroll
    for (int a = 0; a < 4; a++)
#pragma unroll
        for (int b = 0; b < 4; b++)
#pragma unroll
            for (int q = 0; q < 4; q++) acc[a][b][q] = 0.f;

    // per-thread ldmatrix address pieces
    const int aRow = wm * 64 + (lane & 15);
    const uint32_t aXor = ((uint32_t)aRow & 7u) << 4;
    const uint32_t aKb = ((uint32_t)lane >> 4) << 4;
    const uint32_t aRowOff = (uint32_t)aRow * 128u;
    const int bRow = wn * 32 + (lane & 7) + (((lane >> 4) & 1) << 3);
    const uint32_t bXor = ((uint32_t)bRow & 7u) << 4;
    const uint32_t bKb = (((uint32_t)lane >> 3) & 1u) << 4;
    const uint32_t bRowOff = (uint32_t)bRow * 128u;

    for (int c = 0; c < NC; c++) {
        const int st = c & 1;
        const uint32_t aSt = sb + (uint32_t)st * 32768u;
        const uint32_t wSt = sb + SW_OFF + (uint32_t)st * W_STAGE;

#pragma unroll
        for (int kk = 0; kk < 4; kk++) {
            const uint32_t kA = ((uint32_t)(kk * 32) + aKb) ^ aXor;
            const uint32_t kB = ((uint32_t)(kk * 32) + bKb) ^ bXor;
            uint32_t bfh[8], af[4][4];
#pragma unroll
            for (int g = 0; g < 2; g++)
                ldsm4(&bfh[4 * g], wSt + bRowOff + (uint32_t)g * 2048u + kB);
#pragma unroll
            for (int mf = 0; mf < 4; mf++)
                ldsm4(af[mf], aSt + aRowOff + (uint32_t)mf * 2048u + kA);
#pragma unroll
            for (int mf = 0; mf < 4; mf++)
#pragma unroll
                for (int nf = 0; nf < 4; nf++)
                    mma16816(acc[mf][nf], af[mf], &bfh[2 * nf]);
        }

        __syncthreads();
        if (c + 2 < NC) {
            load_chunk(aSt, wSt, (c + 2) * 64);
            CP_COMMIT();
            CP_WAIT1();
        } else {
            CP_WAIT0();
        }
        __syncthreads();
    }

    // ---- epilogue: blended bias + ELU, direct float2 stores ----
#pragma unroll
    for (int mf = 0; mf < 4; mf++) {
        const int r0 = wm * 64 + mf * 16 + (lane >> 2);
        const int r1 = r0 + 8;
        float bcv0[NE], bcv1[NE];
#pragma unroll
        for (int e = 0; e < NE; e++) { bcv0[e] = bcs[r0 * 8 + e]; bcv1[e] = bcs[r1 * 8 + e]; }
#pragma unroll
        for (int nf = 0; nf < 4; nf++) {
            const int cl = wn * 32 + nf * 8 + ((lane & 3) << 1);
            float bb00 = 0.f, bb01 = 0.f, bb10 = 0.f, bb11 = 0.f;
#pragma unroll
            for (int e = 0; e < NE; e++) {
                float be0 = bias_s[e * BN + cl], be1 = bias_s[e * BN + cl + 1];
                bb00 = fmaf(bcv0[e], be0, bb00);
                bb01 = fmaf(bcv0[e], be1, bb01);
                bb10 = fmaf(bcv1[e], be0, bb10);
                bb11 = fmaf(bcv1[e], be1, bb11);
            }
            float v00 = acc[mf][nf][0] + bb00;
            float v01 = acc[mf][nf][1] + bb01;
            float v10 = acc[mf][nf][2] + bb10;
            float v11 = acc[mf][nf][3] + bb11;
            if (applyElu) {
                v00 = (v00 > 0.f) ? v00 : expm1f(v00);
                v01 = (v01 > 0.f) ? v01 : expm1f(v01);
                v10 = (v10 > 0.f) ? v10 : expm1f(v10);
                v11 = (v11 > 0.f) ? v11 : expm1f(v11);
            }
            const int gc = nBase + cl;
            *reinterpret_cast<float2*>(C + (size_t)(mBase + r0) * ldc + gc) =
                make_float2(v00, v01);
            *reinterpret_cast<float2*>(C + (size_t)(mBase + r1) * ldc + gc) =
                make_float2(v10, v11);
        }
    }
}

// ===========================================================================
// gate GEMM: BM=32, BN=128(=Nout), BK=16, elu. grid = 4096/32 = 128
// ===========================================================================
__global__ __launch_bounds__(256, 4)
void gate_gemm_kernel(const float* __restrict__ A, int IN,
                      const float* __restrict__ W,   // [128][IN]
                      const float* __restrict__ bias,
                      float* __restrict__ C) {
    __shared__ float As[16][32];
    __shared__ float Bs[16][128];
    const int tid = threadIdx.x;
    const int tx = tid & 15, ty = tid >> 4;
    const int mBase = blockIdx.x * 32;

    float acc[2][8];
#pragma unroll
    for (int i = 0; i < 2; i++)
#pragma unroll
        for (int j = 0; j < 8; j++) acc[i][j] = 0.f;

    const int r2 = tid >> 2;
    const int vec = (tid & 3) << 2;

    for (int k0 = 0; k0 < IN; k0 += 16) {
        if (tid < 128) {
            int r = tid >> 2;
            float4 v = *reinterpret_cast<const float4*>(A + (size_t)(mBase + r) * IN + k0 + vec);
            As[vec + 0][r] = v.x; As[vec + 1][r] = v.y;
            As[vec + 2][r] = v.z; As[vec + 3][r] = v.w;
        }
#pragma unroll
        for (int rr = 0; rr < 2; rr++) {
            int o = r2 + rr * 64;
            float4 v = *reinterpret_cast<const float4*>(W + (size_t)o * IN + k0 + vec);
            Bs[vec + 0][o] = v.x; Bs[vec + 1][o] = v.y;
            Bs[vec + 2][o] = v.z; Bs[vec + 3][o] = v.w;
        }
        __syncthreads();
#pragma unroll
        for (int k = 0; k < 16; k++) {
            float a0 = As[k][ty * 2], a1 = As[k][ty * 2 + 1];
            float4 b0 = *reinterpret_cast<const float4*>(&Bs[k][tx * 8]);
            float4 b1 = *reinterpret_cast<const float4*>(&Bs[k][tx * 8 + 4]);
            float bv[8] = {b0.x, b0.y, b0.z, b0.w, b1.x, b1.y, b1.z, b1.w};
#pragma unroll
            for (int j = 0; j < 8; j++) {
                acc[0][j] = fmaf(a0, bv[j], acc[0][j]);
                acc[1][j] = fmaf(a1, bv[j], acc[1][j]);
            }
        }
        __syncthreads();
    }
#pragma unroll
    for (int i = 0; i < 2; i++) {
        int grow = mBase + ty * 2 + i;
#pragma unroll
        for (int j = 0; j < 8; j++) {
            int gcol = tx * 8 + j;
            float v = acc[i][j] + __ldg(bias + gcol);
            v = (v > 0.f) ? v : expm1f(v);
            C[(size_t)grow * GHD + gcol] = v;
        }
    }
}

// ===========================================================================
// gate3 + softmax (one warp per row)
// ===========================================================================
__global__ void gate3_softmax_kernel(const float* __restrict__ H2,
                                     const float* __restrict__ Wg3,
                                     const float* __restrict__ bg3,
                                     float* __restrict__ BC) {
    int warp = (blockIdx.x * blockDim.x + threadIdx.x) >> 5;
    int lane = threadIdx.x & 31;
    if (warp >= MB) return;
    const float* h = H2 + (size_t)warp * GHD;
    float hv[4];
#pragma unroll
    for (int t = 0; t < 4; t++) hv[t] = h[lane + 32 * t];
    float s[NE];
#pragma unroll
    for (int e = 0; e < NE; e++) {
        float p = 0.f;
#pragma unroll
        for (int t = 0; t < 4; t++)
            p = fmaf(hv[t], __ldg(Wg3 + e * GHD + lane + 32 * t), p);
#pragma unroll
        for (int off = 16; off > 0; off >>= 1) p += __shfl_xor_sync(0xFFFFFFFFu, p, off);
        s[e] = p + __ldg(bg3 + e);
    }
    float mx = s[0];
#pragma unroll
    for (int e = 1; e < NE; e++) mx = fmaxf(mx, s[e]);
    float sum = 0.f;
#pragma unroll
    for (int e = 0; e < NE; e++) { s[e] = expf(s[e] - mx); sum += s[e]; }
    float inv = 1.f / sum;
    if (lane < NE) BC[(size_t)warp * NE + lane] = s[lane] * inv;
}

// ===========================================================================
extern "C" void kernel_launch(void* const* d_in, const int* in_sizes, int n_in,
                              void* d_out, int out_size) {
    const float* x   = (const float*)d_in[0];
    const float* z   = (const float*)d_in[1];
    const float* Wg1 = (const float*)d_in[2];
    const float* bg1 = (const float*)d_in[3];
    const float* Wg2 = (const float*)d_in[4];
    const float* bg2 = (const float*)d_in[5];
    const float* Wg3 = (const float*)d_in[6];
    const float* bg3 = (const float*)d_in[7];
    const float* W0  = (const float*)d_in[8];
    const float* b0  = (const float*)d_in[9];
    const float* W1  = (const float*)d_in[10];
    const float* b1  = (const float*)d_in[11];
    const float* W2  = (const float*)d_in[12];
    const float* b2  = (const float*)d_in[13];
    const float* W3  = (const float*)d_in[14];
    const float* b3  = (const float*)d_in[15];
    float* out = (float*)d_out;

    float *G, *H1, *H2, *BC, *HA, *HB;
    __half *Ah, *W0h, *W1h, *W2h, *W3h;
    cudaGetSymbolAddress((void**)&G,  g_G);
    cudaGetSymbolAddress((void**)&H1, g_H1);
    cudaGetSymbolAddress((void**)&H2, g_H2);
    cudaGetSymbolAddress((void**)&BC, g_BC);
    cudaGetSymbolAddress((void**)&HA, g_HA);
    cudaGetSymbolAddress((void**)&HB, g_HB);
    cudaGetSymbolAddress((void**)&Ah, g_Ah);
    cudaGetSymbolAddress((void**)&W0h, g_W0h);
    cudaGetSymbolAddress((void**)&W1h, g_W1h);
    cudaGetSymbolAddress((void**)&W2h, g_W2h);
    cudaGetSymbolAddress((void**)&W3h, g_W3h);

    cudaFuncSetAttribute(moe_hmma_gemm<4>, cudaFuncAttributeMaxDynamicSharedMemorySize, 110592);
    cudaFuncSetAttribute(moe_hmma_gemm<3>, cudaFuncAttributeMaxDynamicSharedMemorySize, 101376);

    // prep + gate network
    prep_kernel<<<(MB * GW + 255) / 256, 256>>>(x, z, G, HA, HB);
    gate_gemm_kernel<<<MB / 32, 256>>>(G, GW, Wg1, bg1, H1);
    gate_gemm_kernel<<<MB / 32, 256>>>(H1, GHD, Wg2, bg2, H2);
    gate3_softmax_kernel<<<(MB * 32 + 255) / 256, 256>>>(H2, Wg3, bg3, BC);

    // layer 0: inp = G [MB,864], Kp = 6912 -> HA[:, :1024], elu
    {
        wconv_kernel<<<dim3((GW / 4 + 255) / 256, HD, NE), 256>>>(W0, W0h, HD, GW);
        asplit_kernel<<<dim3((GW / 8 + 127) / 128, MB), 128>>>(G, GW, GW, BC, Ah, KP0);
        moe_hmma_gemm<4><<<dim3(HD / 128, MB / BM), 512, 110592>>>(
            Ah, W0h, KP0, b0, BC, HD, HA, HW, 1);
    }
    // layer 1: inp = HA [MB,1088], Kp = 8704 -> HB[:, :1024], elu
    {
        wconv_kernel<<<dim3((HW / 4 + 255) / 256, HD, NE), 256>>>(W1, W1h, HD, HW);
        asplit_kernel<<<dim3((HW / 8 + 127) / 128, MB), 128>>>(HA, HW, HW, BC, Ah, KP1);
        moe_hmma_gemm<4><<<dim3(HD / 128, MB / BM), 512, 110592>>>(
            Ah, W1h, KP1, b1, BC, HD, HB, HW, 1);
    }
    // layer 2: inp = HB -> HA[:, :1024], elu
    {
        wconv_kernel<<<dim3((HW / 4 + 255) / 256, HD, NE), 256>>>(W2, W2h, HD, HW);
        asplit_kernel<<<dim3((HW / 8 + 127) / 128, MB), 128>>>(HB, HW, HW, BC, Ah, KP1);
        moe_hmma_gemm<4><<<dim3(HD / 128, MB / BM), 512, 110592>>>(
            Ah, W2h, KP1, b2, BC, HD, HA, HW, 1);
    }
    // layer 3: inp = HA cols 0..1023 (IN=1024, lda=1088), Kp = 8192 -> out
    // BN=96 variant: grid 8x16 = 128 CTAs
    {
        wconv_kernel<<<dim3((HD / 4 + 255) / 256, OD, NE), 256>>>(W3, W3h, OD, HD);
        asplit_kernel<<<dim3((HD / 8 + 127) / 128, MB), 128>>>(HA, HW, HD, BC, Ah, KP3);
        moe_hmma_gemm<3><<<dim3(OD / 96, MB / BM), 384, 101376>>>(
            Ah, W3h, KP3, b3, BC, OD, out, OD, 0);
    }
}